// round 2
// baseline (speedup 1.0000x reference)
#include <cuda_runtime.h>

// NextState: x' = x + dt * f(x); quaternion kinematics + velocity integrate.
// K rows; state[K,13] = [pos(3), quat(4: x,y,z,w), vel(6)]; delta[K,6].
// out[K,13] = [pos + dt*R(q)*v_lin, normalize(q + dt*T(q)*v_ang), vel + delta].
//
// Memory-bound: 256 MB total traffic. Strategy: shared-memory staging so every
// global transaction is a coalesced 128-bit float4; compute reads smem with
// stride 13 (coprime with 32 banks -> conflict-free).

#define DT   0.1f
#define EPSQ 1e-12f

#define TPB      256
#define ROWS_PB  256            // rows per block (== TPB, 1 row/thread)
#define S_F4     (ROWS_PB * 13 / 4)   // 832 float4 of state per block
#define D_F4     (ROWS_PB * 6 / 4)    // 384 float4 of delta per block

__global__ __launch_bounds__(TPB, 8)
void nextstate_kernel(const float* __restrict__ state,
                      const float* __restrict__ delta,
                      float* __restrict__ out,
                      int K)
{
    __shared__ float s_state[ROWS_PB * 13];   // 13312 B; reused as output stage
    __shared__ float s_delta[ROWS_PB * 6];    //  6144 B

    const int t       = threadIdx.x;
    const int rowBase = blockIdx.x * ROWS_PB;

    // ---- Stage inputs: fully coalesced float4 loads ----
    // Block b's state span: floats [rowBase*13, rowBase*13 + 3328); 3328 % 4 == 0
    // so block boundaries are float4 aligned. Same for delta (1536 % 4 == 0).
    {
        const float4* g4 = (const float4*)state;
        float4*       s4 = (float4*)s_state;
        const int base4  = rowBase * 13 / 4;
        const int tot4   = K * 13 / 4;          // K*13 is divisible by 4 (K even)
        #pragma unroll
        for (int i = 0; i < (S_F4 + TPB - 1) / TPB; ++i) {
            int idx = t + i * TPB;
            if (idx < S_F4) {
                int g = base4 + idx;
                if (g < tot4) s4[idx] = g4[g];
            }
        }
    }
    {
        const float4* g4 = (const float4*)delta;
        float4*       s4 = (float4*)s_delta;
        const int base4  = rowBase * 6 / 4;
        const int tot4   = K * 6 / 4;
        #pragma unroll
        for (int i = 0; i < (D_F4 + TPB - 1) / TPB; ++i) {
            int idx = t + i * TPB;
            if (idx < D_F4) {
                int g = base4 + idx;
                if (g < tot4) s4[idx] = g4[g];
            }
        }
    }
    __syncthreads();

    // ---- Compute one row per thread (smem stride 13: conflict-free) ----
    float r[13];
    const int row = rowBase + t;
    const bool valid = (row < K);
    if (valid) {
        const float* s = &s_state[t * 13];
        const float* d = &s_delta[t * 6];

        const float px = s[0],  py = s[1],  pz = s[2];
        const float qx = s[3],  qy = s[4],  qz = s[5],  qw = s[6];
        const float v0 = s[7],  v1 = s[8],  v2 = s[9];
        const float w0 = s[10], w1 = s[11], w2 = s[12];

        // R(q) * v_lin
        const float xx = qx*qx, yy = qy*qy, zz = qz*qz;
        const float xy = qx*qy, xz = qx*qz, yz = qy*qz;
        const float xw = qx*qw, yw = qy*qw, zw = qz*qw;

        const float pd0 = (1.0f - 2.0f*(yy + zz))*v0 + 2.0f*(xy - zw)*v1 + 2.0f*(xz + yw)*v2;
        const float pd1 = 2.0f*(xy + zw)*v0 + (1.0f - 2.0f*(xx + zz))*v1 + 2.0f*(yz - xw)*v2;
        const float pd2 = 2.0f*(xz - yw)*v0 + 2.0f*(yz + xw)*v1 + (1.0f - 2.0f*(xx + yy))*v2;

        // T(q) * v_ang  (0.5 factor folded)
        const float qd0 = 0.5f * (-qx*w0 - qy*w1 - qz*w2);
        const float qd1 = 0.5f * ( qw*w0 - qz*w1 + qy*w2);
        const float qd2 = 0.5f * ( qz*w0 + qw*w1 - qx*w2);
        const float qd3 = 0.5f * (-qy*w0 + qx*w1 + qw*w2);

        float nqx = qx + DT*qd0;
        float nqy = qy + DT*qd1;
        float nqz = qz + DT*qd2;
        float nqw = qw + DT*qd3;
        const float sq = nqx*nqx + nqy*nqy + nqz*nqz + nqw*nqw;
        const float inv = rsqrtf(fmaxf(sq, EPSQ));

        r[0] = px + DT*pd0;  r[1] = py + DT*pd1;  r[2] = pz + DT*pd2;
        r[3] = nqx*inv;      r[4] = nqy*inv;      r[5] = nqz*inv;     r[6] = nqw*inv;
        r[7] = v0 + d[0];    r[8] = v1 + d[1];    r[9] = v2 + d[2];
        r[10] = w0 + d[3];   r[11] = w1 + d[4];   r[12] = w2 + d[5];
    }

    // ---- Stage output into (reused) state smem, then coalesced float4 stores ----
    __syncthreads();             // everyone done READING s_state before overwrite
    if (valid) {
        #pragma unroll
        for (int i = 0; i < 13; ++i) s_state[t * 13 + i] = r[i];
    }
    __syncthreads();

    {
        float4*       g4 = (float4*)out;
        const float4* s4 = (const float4*)s_state;
        const int base4  = rowBase * 13 / 4;
        const int tot4   = K * 13 / 4;
        #pragma unroll
        for (int i = 0; i < (S_F4 + TPB - 1) / TPB; ++i) {
            int idx = t + i * TPB;
            if (idx < S_F4) {
                int g = base4 + idx;
                if (g < tot4) g4[g] = s4[idx];
            }
        }
    }
}

extern "C" void kernel_launch(void* const* d_in, const int* in_sizes, int n_in,
                              void* d_out, int out_size)
{
    const float* state = (const float*)d_in[0];   // K*13 floats
    const float* delta = (const float*)d_in[1];   // K*6 floats
    float*       out   = (float*)d_out;           // K*13 floats

    const int K = in_sizes[0] / 13;
    const int grid = (K + ROWS_PB - 1) / ROWS_PB;
    nextstate_kernel<<<grid, TPB>>>(state, delta, out, K);
}

// round 4
// speedup vs baseline: 1.0888x; 1.0888x over previous
#include <cuda_runtime.h>
#include <cstdint>

// NextState on sm_100a — HBM-bound (256 MB traffic, ~0.5 flop/B).
// Bulk-async (TMA) copies gmem<->smem in both directions: no register-file
// round trip for the bulk data. Compute is in-place on the thread's own
// smem row (stride 13, coprime with 32 banks -> conflict-free).

#define DT   0.1f
#define EPSQ 1e-12f

#define TPB      512
#define ROWS_PB  512
#define S_FLOATS (ROWS_PB * 13)   // 6656 floats = 26624 B
#define D_FLOATS (ROWS_PB * 6)    // 3072 floats = 12288 B

__device__ __forceinline__ uint32_t smem_u32(const void* p) {
    return (uint32_t)__cvta_generic_to_shared(p);
}

__global__ __launch_bounds__(TPB, 4)
void nextstate_kernel(const float* __restrict__ state,
                      const float* __restrict__ delta,
                      float* __restrict__ out,
                      int K)
{
    __shared__ alignas(16) float s_state[S_FLOATS];  // in+out (in-place)
    __shared__ alignas(16) float s_delta[D_FLOATS];
    __shared__ alignas(8)  uint64_t mbar;

    const int t       = threadIdx.x;
    const int rowBase = blockIdx.x * ROWS_PB;
    const int rows    = min(ROWS_PB, K - rowBase);

    const int sFloats = rows * 13;
    const int dFloats = rows * 6;
    const int sBulkF  = sFloats & ~3;          // 16B-multiple portion (floats)
    const int dBulkF  = dFloats & ~3;
    const int sRem    = sFloats - sBulkF;      // 0..3 floats
    const int dRem    = dFloats - dBulkF;

    const uint32_t mb  = smem_u32(&mbar);
    const uint32_t sSt = smem_u32(s_state);
    const uint32_t sDl = smem_u32(s_delta);

    // ---- init mbarrier; issue bulk-async loads (thread 0 only) ----
    if (t == 0) {
        asm volatile("mbarrier.init.shared.b64 [%0], %1;" :: "r"(mb), "r"(1));
        asm volatile("fence.proxy.async.shared::cta;" ::: "memory");
        const uint32_t txBytes = (uint32_t)(sBulkF + dBulkF) * 4u;
        asm volatile("mbarrier.arrive.expect_tx.shared.b64 _, [%0], %1;"
                     :: "r"(mb), "r"(txBytes) : "memory");
        asm volatile(
            "cp.async.bulk.shared::cta.global.mbarrier::complete_tx::bytes "
            "[%0], [%1], %2, [%3];"
            :: "r"(sSt), "l"(state + (size_t)rowBase * 13),
               "r"((uint32_t)sBulkF * 4u), "r"(mb) : "memory");
        asm volatile(
            "cp.async.bulk.shared::cta.global.mbarrier::complete_tx::bytes "
            "[%0], [%1], %2, [%3];"
            :: "r"(sDl), "l"(delta + (size_t)rowBase * 6),
               "r"((uint32_t)dBulkF * 4u), "r"(mb) : "memory");
    }
    // barrier now initialized & visible to all threads before anyone waits
    __syncthreads();

    // scalar remainder (only when tile bytes aren't a 16B multiple)
    if (t < sRem) s_state[sBulkF + t] = state[(size_t)rowBase * 13 + sBulkF + t];
    if (t < dRem) s_delta[dBulkF + t] = delta[(size_t)rowBase * 6  + dBulkF + t];

    // ---- wait for TMA completion (phase 0) ----
    {
        uint32_t done;
        asm volatile(
            "{\n\t.reg .pred p;\n\t"
            "mbarrier.try_wait.parity.shared.b64 p, [%1], 0;\n\t"
            "selp.b32 %0, 1, 0, p;\n\t}"
            : "=r"(done) : "r"(mb) : "memory");
        if (!done) {
            asm volatile(
                "{\n\t.reg .pred P1;\n\t"
                "WAIT_LOOP:\n\t"
                "mbarrier.try_wait.parity.shared.b64 P1, [%0], 0;\n\t"
                "@P1 bra.uni WAIT_DONE;\n\t"
                "bra.uni WAIT_LOOP;\n\t"
                "WAIT_DONE:\n\t}"
                :: "r"(mb) : "memory");
        }
    }

    // ---- compute, in place: thread t owns row t (no cross-thread deps) ----
    if (t < rows) {
        float* s = &s_state[t * 13];
        const float* d = &s_delta[t * 6];

        const float px = s[0],  py = s[1],  pz = s[2];
        const float qx = s[3],  qy = s[4],  qz = s[5],  qw = s[6];
        const float v0 = s[7],  v1 = s[8],  v2 = s[9];
        const float w0 = s[10], w1 = s[11], w2 = s[12];

        const float xx = qx*qx, yy = qy*qy, zz = qz*qz;
        const float xy = qx*qy, xz = qx*qz, yz = qy*qz;
        const float xw = qx*qw, yw = qy*qw, zw = qz*qw;

        const float pd0 = (1.0f - 2.0f*(yy + zz))*v0 + 2.0f*(xy - zw)*v1 + 2.0f*(xz + yw)*v2;
        const float pd1 = 2.0f*(xy + zw)*v0 + (1.0f - 2.0f*(xx + zz))*v1 + 2.0f*(yz - xw)*v2;
        const float pd2 = 2.0f*(xz - yw)*v0 + 2.0f*(yz + xw)*v1 + (1.0f - 2.0f*(xx + yy))*v2;

        const float qd0 = 0.5f * (-qx*w0 - qy*w1 - qz*w2);
        const float qd1 = 0.5f * ( qw*w0 - qz*w1 + qy*w2);
        const float qd2 = 0.5f * ( qz*w0 + qw*w1 - qx*w2);
        const float qd3 = 0.5f * (-qy*w0 + qx*w1 + qw*w2);

        const float nqx = qx + DT*qd0;
        const float nqy = qy + DT*qd1;
        const float nqz = qz + DT*qd2;
        const float nqw = qw + DT*qd3;
        const float sq  = nqx*nqx + nqy*nqy + nqz*nqz + nqw*nqw;
        const float inv = rsqrtf(fmaxf(sq, EPSQ));

        s[0]  = px + DT*pd0;  s[1]  = py + DT*pd1;  s[2]  = pz + DT*pd2;
        s[3]  = nqx*inv;      s[4]  = nqy*inv;      s[5]  = nqz*inv;  s[6] = nqw*inv;
        s[7]  = v0 + d[0];    s[8]  = v1 + d[1];    s[9]  = v2 + d[2];
        s[10] = w0 + d[3];    s[11] = w1 + d[4];    s[12] = w2 + d[5];
    }

    // all rows written before the bulk store reads smem
    __syncthreads();

    // ---- bulk-async store: smem -> gmem ----
    if (t == 0) {
        asm volatile("fence.proxy.async.shared::cta;" ::: "memory");
        asm volatile(
            "cp.async.bulk.global.shared::cta.bulk_group [%0], [%1], %2;"
            :: "l"(out + (size_t)rowBase * 13), "r"(sSt),
               "r"((uint32_t)sBulkF * 4u) : "memory");
        asm volatile("cp.async.bulk.commit_group;" ::: "memory");
    }
    if (t < sRem) out[(size_t)rowBase * 13 + sBulkF + t] = s_state[sBulkF + t];

    if (t == 0) {
        // smem must stay alive until the bulk store's smem reads complete
        asm volatile("cp.async.bulk.wait_group.read 0;" ::: "memory");
    }
}

extern "C" void kernel_launch(void* const* d_in, const int* in_sizes, int n_in,
                              void* d_out, int out_size)
{
    const float* state = (const float*)d_in[0];   // K*13 floats
    const float* delta = (const float*)d_in[1];   // K*6 floats
    float*       out   = (float*)d_out;           // K*13 floats

    const int K = in_sizes[0] / 13;
    const int grid = (K + ROWS_PB - 1) / ROWS_PB;
    nextstate_kernel<<<grid, TPB>>>(state, delta, out, K);
}